// round 2
// baseline (speedup 1.0000x reference)
#include <cuda_runtime.h>
#include <math.h>

#define BB 2
#define SS 2048
#define DD 1024
#define HH 16
#define HDIM 64
#define MTOT (BB*SS)      // 4096
#define NN 1024
#define KK 1024

// ---------------- scratch (no allocations allowed) ----------------
__device__ float g_Q[(size_t)BB*HH*SS*HDIM];
__device__ float g_K[(size_t)BB*HH*SS*HDIM];
__device__ float g_V[(size_t)BB*HH*SS*HDIM];
__device__ float g_ctx[(size_t)BB*SS*DD];

// ---------------- SGEMM 128x128x8, 8x8 per thread ----------------
// C[M=4096, N=1024] = A[M, K=1024] @ W[K, N] + bias
// MODE 0: plain row-major out[m*N+n]
// MODE 1: scatter to [b][h][s][hd] (QKV layout)
template<int MODE>
__global__ __launch_bounds__(256) void sgemm_kernel(const float* __restrict__ A,
                                                    const float* __restrict__ W,
                                                    const float* __restrict__ bias,
                                                    float* __restrict__ out)
{
    __shared__ float As[8][132];   // A^T fragment: As[k][m_local]
    __shared__ float Bs[8][132];   // Bs[k][n_local]

    const int tid = threadIdx.x;
    const int tx = tid & 15;
    const int ty = tid >> 4;
    const int m_blk = blockIdx.y * 128;
    const int n_blk = blockIdx.x * 128;

    const int a_row = tid >> 1;          // 0..127
    const int a_k   = (tid & 1) * 4;     // 0 or 4
    const int b_k   = tid >> 5;          // 0..7
    const int b_col = (tid & 31) * 4;    // 0..124

    const float* Aptr = A + (size_t)(m_blk + a_row) * KK + a_k;
    const float* Wptr = W + (size_t)b_k * NN + n_blk + b_col;

    float acc[8][8];
#pragma unroll
    for (int i = 0; i < 8; i++)
#pragma unroll
        for (int j = 0; j < 8; j++) acc[i][j] = 0.f;

    for (int k0 = 0; k0 < KK; k0 += 8) {
        float4 av = *(const float4*)(Aptr + k0);
        float4 bv = *(const float4*)(Wptr + (size_t)k0 * NN);
        As[a_k + 0][a_row] = av.x;
        As[a_k + 1][a_row] = av.y;
        As[a_k + 2][a_row] = av.z;
        As[a_k + 3][a_row] = av.w;
        *(float4*)&Bs[b_k][b_col] = bv;
        __syncthreads();
#pragma unroll
        for (int kk = 0; kk < 8; kk++) {
            float4 a0 = *(float4*)&As[kk][ty * 8];
            float4 a1 = *(float4*)&As[kk][ty * 8 + 4];
            float4 b0 = *(float4*)&Bs[kk][tx * 8];
            float4 b1 = *(float4*)&Bs[kk][tx * 8 + 4];
            float a[8] = {a0.x, a0.y, a0.z, a0.w, a1.x, a1.y, a1.z, a1.w};
            float b[8] = {b0.x, b0.y, b0.z, b0.w, b1.x, b1.y, b1.z, b1.w};
#pragma unroll
            for (int i = 0; i < 8; i++)
#pragma unroll
                for (int j = 0; j < 8; j++)
                    acc[i][j] = fmaf(a[i], b[j], acc[i][j]);
        }
        __syncthreads();
    }

    // epilogue
#pragma unroll
    for (int i = 0; i < 8; i++) {
        const int m = m_blk + ty * 8 + i;
#pragma unroll
        for (int jc = 0; jc < 8; jc += 4) {
            const int n = n_blk + tx * 8 + jc;
            float4 r;
            r.x = acc[i][jc + 0] + bias[n + 0];
            r.y = acc[i][jc + 1] + bias[n + 1];
            r.z = acc[i][jc + 2] + bias[n + 2];
            r.w = acc[i][jc + 3] + bias[n + 3];
            if (MODE == 0) {
                *(float4*)&out[(size_t)m * NN + n] = r;
            } else {
                const int b = m / SS, s = m % SS;
                const int h = n / HDIM, hd = n % HDIM;
                *(float4*)&out[((((size_t)b * HH + h) * SS + s) * HDIM) + hd] = r;
            }
        }
    }
}

// ---------------- fused flash attention ----------------
// grid: (S/64, H, B); block 256 threads = 16x16, 4x4 microtiles.
// smem: QT[64][68] (Q^T), KT[64][68] (K^T), Vs[64][68], PT[64][68] (P^T)
#define LDA 68
#define SM_BYTES (4 * 64 * LDA * 4)

__global__ __launch_bounds__(256) void attn_kernel(const int* __restrict__ mask,
                                                   const float* __restrict__ cmw)
{
    extern __shared__ float sm[];
    float* QT = sm;
    float* KT = sm + 64 * LDA;
    float* Vs = sm + 2 * 64 * LDA;
    float* PT = sm + 3 * 64 * LDA;
    __shared__ float s_bias;

    const int tid = threadIdx.x;
    const int tx = tid & 15;
    const int ty = tid >> 4;
    const int qt = blockIdx.x;
    const int h  = blockIdx.y;
    const int b  = blockIdx.z;
    const int q0g = qt * 64;

    if (tid == 0) {
        float sum = 0.f;
        for (int i = 0; i < 9; i++) sum += cmw[i];
        s_bias = sum / 9.0f;
    }

    // load Q tile transposed: QT[k][q]
    {
        const int ql = tid >> 2;            // 0..63
        const int k0 = (tid & 3) * 16;      // 0,16,32,48
        const float* qp = g_Q + ((((size_t)b * HH + h) * SS + q0g + ql) * HDIM) + k0;
#pragma unroll
        for (int c = 0; c < 4; c++) {
            float4 v = *(const float4*)(qp + c * 4);
            QT[(k0 + c * 4 + 0) * LDA + ql] = v.x;
            QT[(k0 + c * 4 + 1) * LDA + ql] = v.y;
            QT[(k0 + c * 4 + 2) * LDA + ql] = v.z;
            QT[(k0 + c * 4 + 3) * LDA + ql] = v.w;
        }
    }
    __syncthreads();
    const float mbias = s_bias;

    float m_st[4], l_st[4], acc[4][4];
#pragma unroll
    for (int i = 0; i < 4; i++) {
        m_st[i] = -INFINITY;
        l_st[i] = 0.f;
#pragma unroll
        for (int j = 0; j < 4; j++) acc[i][j] = 0.f;
    }

    const int rl = tid >> 2;
    const int c0 = (tid & 3) * 16;
    const float* kbase = g_K + ((((size_t)b * HH + h) * SS) * HDIM);
    const float* vbase = g_V + ((((size_t)b * HH + h) * SS) * HDIM);

    for (int jt = 0; jt < 32; jt++) {
        const int j0g = jt * 64;

        // prefetch K/V tiles into registers (before barrier)
        float4 kv[4], vv[4];
        const float* kp = kbase + (size_t)(j0g + rl) * HDIM + c0;
        const float* vp = vbase + (size_t)(j0g + rl) * HDIM + c0;
#pragma unroll
        for (int c = 0; c < 4; c++) {
            kv[c] = *(const float4*)(kp + c * 4);
            vv[c] = *(const float4*)(vp + c * 4);
        }
        // mask values for my 4x4 score microtile
        int4 mv[4];
#pragma unroll
        for (int qi = 0; qi < 4; qi++) {
            mv[qi] = *(const int4*)&mask[((size_t)b * SS + (q0g + ty * 4 + qi)) * SS
                                         + j0g + tx * 4];
        }

        __syncthreads();   // previous iter's PxV done reading Vs/PT
#pragma unroll
        for (int c = 0; c < 4; c++) {
            KT[(c0 + c * 4 + 0) * LDA + rl] = kv[c].x;
            KT[(c0 + c * 4 + 1) * LDA + rl] = kv[c].y;
            KT[(c0 + c * 4 + 2) * LDA + rl] = kv[c].z;
            KT[(c0 + c * 4 + 3) * LDA + rl] = kv[c].w;
            *(float4*)&Vs[rl * LDA + c0 + c * 4] = vv[c];
        }
        __syncthreads();

        // scores: sc[qi][ji] = Q[q] . K[j]
        float sc[4][4];
#pragma unroll
        for (int i = 0; i < 4; i++)
#pragma unroll
            for (int j = 0; j < 4; j++) sc[i][j] = 0.f;

#pragma unroll 8
        for (int k = 0; k < 64; k++) {
            float4 qv = *(float4*)&QT[k * LDA + ty * 4];
            float4 kw = *(float4*)&KT[k * LDA + tx * 4];
            float qa[4] = {qv.x, qv.y, qv.z, qv.w};
            float ka[4] = {kw.x, kw.y, kw.z, kw.w};
#pragma unroll
            for (int i = 0; i < 4; i++)
#pragma unroll
                for (int j = 0; j < 4; j++)
                    sc[i][j] = fmaf(qa[i], ka[j], sc[i][j]);
        }

        // scale + bias + mask
#pragma unroll
        for (int qi = 0; qi < 4; qi++) {
            const int mm[4] = {mv[qi].x, mv[qi].y, mv[qi].z, mv[qi].w};
#pragma unroll
            for (int ji = 0; ji < 4; ji++) {
                float v = sc[qi][ji] * 0.125f + mbias;
                sc[qi][ji] = (mm[ji] == 0) ? -1e9f : v;
            }
        }

        // online softmax (row stats over tx via shuffle: lane bits 0..3 = tx)
#pragma unroll
        for (int qi = 0; qi < 4; qi++) {
            float rmax = fmaxf(fmaxf(sc[qi][0], sc[qi][1]), fmaxf(sc[qi][2], sc[qi][3]));
#pragma unroll
            for (int off = 1; off < 16; off <<= 1)
                rmax = fmaxf(rmax, __shfl_xor_sync(0xffffffffu, rmax, off));
            const float m_new = fmaxf(m_st[qi], rmax);
            const float corr = __expf(m_st[qi] - m_new);
            m_st[qi] = m_new;
            float rsum = 0.f;
#pragma unroll
            for (int ji = 0; ji < 4; ji++) {
                const float p = __expf(sc[qi][ji] - m_new);
                sc[qi][ji] = p;
                rsum += p;
            }
#pragma unroll
            for (int off = 1; off < 16; off <<= 1)
                rsum += __shfl_xor_sync(0xffffffffu, rsum, off);
            l_st[qi] = l_st[qi] * corr + rsum;
#pragma unroll
            for (int di = 0; di < 4; di++) acc[qi][di] *= corr;
            // write P transposed: PT[j][q]
#pragma unroll
            for (int ji = 0; ji < 4; ji++)
                PT[(tx * 4 + ji) * LDA + ty * 4 + qi] = sc[qi][ji];
        }
        __syncthreads();

        // ctx: acc[qi][di] += sum_j P[q][j] * V[j][d]
#pragma unroll 8
        for (int j = 0; j < 64; j++) {
            float4 pv = *(float4*)&PT[j * LDA + ty * 4];
            float4 vw = *(float4*)&Vs[j * LDA + tx * 4];
            float pa[4] = {pv.x, pv.y, pv.z, pv.w};
            float va[4] = {vw.x, vw.y, vw.z, vw.w};
#pragma unroll
            for (int i = 0; i < 4; i++)
#pragma unroll
                for (int d = 0; d < 4; d++)
                    acc[i][d] = fmaf(pa[i], va[d], acc[i][d]);
        }
    }

    // epilogue: normalize, write ctx [b][s][d]
#pragma unroll
    for (int qi = 0; qi < 4; qi++) {
        const float inv = 1.0f / l_st[qi];
        const int qg = q0g + ty * 4 + qi;
        float4 r;
        r.x = acc[qi][0] * inv;
        r.y = acc[qi][1] * inv;
        r.z = acc[qi][2] * inv;
        r.w = acc[qi][3] * inv;
        *(float4*)&g_ctx[((size_t)b * SS + qg) * DD + h * HDIM + tx * 4] = r;
    }
}

// ---------------- launch ----------------
extern "C" void kernel_launch(void* const* d_in, const int* in_sizes, int n_in,
                              void* d_out, int out_size)
{
    const float* x   = (const float*)d_in[0];
    const float* Wq  = (const float*)d_in[1];
    const float* bq  = (const float*)d_in[2];
    const float* Wk  = (const float*)d_in[3];
    const float* bk  = (const float*)d_in[4];
    const float* Wv  = (const float*)d_in[5];
    const float* bv  = (const float*)d_in[6];
    const float* Wo  = (const float*)d_in[7];
    const float* bo  = (const float*)d_in[8];
    const float* cmw = (const float*)d_in[9];
    const int*  mask = (const int*)d_in[10];
    float* out = (float*)d_out;

    void *pQ, *pK, *pV, *pC;
    cudaGetSymbolAddress(&pQ, g_Q);
    cudaGetSymbolAddress(&pK, g_K);
    cudaGetSymbolAddress(&pV, g_V);
    cudaGetSymbolAddress(&pC, g_ctx);

    dim3 gg(NN / 128, MTOT / 128);
    dim3 bb(256);
    sgemm_kernel<1><<<gg, bb>>>(x, Wq, bq, (float*)pQ);
    sgemm_kernel<1><<<gg, bb>>>(x, Wk, bk, (float*)pK);
    sgemm_kernel<1><<<gg, bb>>>(x, Wv, bv, (float*)pV);

    cudaFuncSetAttribute(attn_kernel, cudaFuncAttributeMaxDynamicSharedMemorySize, SM_BYTES);
    attn_kernel<<<dim3(SS / 64, HH, BB), 256, SM_BYTES>>>(mask, cmw);

    sgemm_kernel<0><<<gg, bb>>>((const float*)pC, Wo, bo, out);
}

// round 4
// speedup vs baseline: 1.3614x; 1.3614x over previous
#include <cuda_runtime.h>
#include <cuda_bf16.h>
#include <cstdint>
#include <math.h>

#define BB 2
#define SS 2048
#define DD 1024
#define HH 16
#define HDIM 64
#define MTOT (BB*SS)      // 4096
#define NN 1024
#define KK 1024

// ---------------- scratch (no allocations allowed) ----------------
__device__ float g_Q[(size_t)BB*HH*SS*HDIM];
__device__ float g_K[(size_t)BB*HH*SS*HDIM];
__device__ float g_V[(size_t)BB*HH*SS*HDIM];
__device__ float g_ctx[(size_t)BB*SS*DD];
__device__ __nv_bfloat16 g_Ah[(size_t)MTOT*KK];
__device__ __nv_bfloat16 g_Al[(size_t)MTOT*KK];
__device__ __nv_bfloat16 g_Wth[(size_t)NN*KK];   // W^T hi  [n][k]
__device__ __nv_bfloat16 g_Wtl[(size_t)NN*KK];   // W^T lo

__device__ __forceinline__ uint32_t smem_u32(const void* p) {
    uint32_t a;
    asm("{ .reg .u64 t; cvta.to.shared.u64 t, %1; cvt.u32.u64 %0, t; }" : "=r"(a) : "l"(p));
    return a;
}

__device__ __forceinline__ void ldsm_x4(uint32_t* r, uint32_t addr) {
    asm volatile("ldmatrix.sync.aligned.m8n8.x4.shared.b16 {%0,%1,%2,%3}, [%4];"
                 : "=r"(r[0]), "=r"(r[1]), "=r"(r[2]), "=r"(r[3]) : "r"(addr));
}

__device__ __forceinline__ void mma16816(float* c, const uint32_t* a, uint32_t b0, uint32_t b1) {
    asm volatile("mma.sync.aligned.m16n8k16.row.col.f32.bf16.bf16.f32 "
                 "{%0,%1,%2,%3}, {%4,%5,%6,%7}, {%8,%9}, {%0,%1,%2,%3};"
                 : "+f"(c[0]), "+f"(c[1]), "+f"(c[2]), "+f"(c[3])
                 : "r"(a[0]), "r"(a[1]), "r"(a[2]), "r"(a[3]), "r"(b0), "r"(b1));
}

// ================= conversion kernels =================
__global__ __launch_bounds__(256) void convx_kernel(const float4* __restrict__ X,
                                                    __nv_bfloat16* __restrict__ H,
                                                    __nv_bfloat16* __restrict__ L)
{
    size_t i = (size_t)blockIdx.x * 256 + threadIdx.x;
    float4 v = X[i];
    __nv_bfloat16 h0 = __float2bfloat16(v.x);
    __nv_bfloat16 h1 = __float2bfloat16(v.y);
    __nv_bfloat16 h2 = __float2bfloat16(v.z);
    __nv_bfloat16 h3 = __float2bfloat16(v.w);
    __nv_bfloat162* H2 = (__nv_bfloat162*)H;
    __nv_bfloat162* L2 = (__nv_bfloat162*)L;
    H2[2*i]   = __nv_bfloat162(h0, h1);
    H2[2*i+1] = __nv_bfloat162(h2, h3);
    L2[2*i]   = __nv_bfloat162(__float2bfloat16(v.x - __bfloat162float(h0)),
                               __float2bfloat16(v.y - __bfloat162float(h1)));
    L2[2*i+1] = __nv_bfloat162(__float2bfloat16(v.z - __bfloat162float(h2)),
                               __float2bfloat16(v.w - __bfloat162float(h3)));
}

// W[k][n] f32 -> Wt_hi/lo[n][k] bf16 (transposed)
__global__ __launch_bounds__(256) void convW_kernel(const float* __restrict__ W,
                                                    __nv_bfloat16* __restrict__ Th,
                                                    __nv_bfloat16* __restrict__ Tl)
{
    __shared__ float t[32][33];
    const int n0 = blockIdx.x * 32, k0 = blockIdx.y * 32;
    const int tx = threadIdx.x, ty = threadIdx.y;  // 32 x 8
#pragma unroll
    for (int r = 0; r < 4; r++)
        t[ty + 8*r][tx] = W[(size_t)(k0 + ty + 8*r) * NN + n0 + tx];
    __syncthreads();
#pragma unroll
    for (int r = 0; r < 4; r++) {
        float v = t[tx][ty + 8*r];       // W[k0+tx][n0+ty+8r]
        __nv_bfloat16 h = __float2bfloat16(v);
        size_t o = (size_t)(n0 + ty + 8*r) * KK + k0 + tx;
        Th[o] = h;
        Tl[o] = __float2bfloat16(v - __bfloat162float(h));
    }
}

// ================= mma.sync bf16-split GEMM =================
// C[4096,1024] = A @ W + bias, via AhBh + AhBl + AlBh (fp32 accum).
// CTA tile 128x128, BK=32. 8 warps: wm in {0,1} (64 rows), wn in {0..3} (32 cols).
// smem rows padded to 40 bf16 (80B) -> conflict-free ldmatrix.
#define SROW 40

template<int MODE>
__global__ __launch_bounds__(256, 2) void gemm_mma_kernel(
    const __nv_bfloat16* __restrict__ Ah, const __nv_bfloat16* __restrict__ Al,
    const __nv_bfloat16* __restrict__ Bh, const __nv_bfloat16* __restrict__ Bl,
    const float* __restrict__ bias, float* __restrict__ out)
{
    __shared__ __nv_bfloat16 sAh[128 * SROW];
    __shared__ __nv_bfloat16 sAl[128 * SROW];
    __shared__ __nv_bfloat16 sBh[128 * SROW];
    __shared__ __nv_bfloat16 sBl[128 * SROW];

    const int tid = threadIdx.x;
    const int wid = tid >> 5;
    const int l   = tid & 31;
    const int wm  = wid >> 2;        // 0..1
    const int wn  = wid & 3;         // 0..3
    const int m_blk = blockIdx.y * 128;
    const int n_blk = blockIdx.x * 128;

    const uint32_t uAh = smem_u32(sAh);
    const uint32_t uAl = smem_u32(sAl);
    const uint32_t uBh = smem_u32(sBh);
    const uint32_t uBl = smem_u32(sBl);

    // ldmatrix lane offsets (bytes)
    const uint32_t a_off = (uint32_t)((wm * 64 + (l & 15)) * SROW + (l >> 4) * 8) * 2;
    const uint32_t b_off = (uint32_t)((wn * 32 + (l & 7) + ((l >> 4) << 3)) * SROW
                                      + ((l >> 3) & 1) * 8) * 2;

    float acc[4][4][4];
#pragma unroll
    for (int i = 0; i < 4; i++)
#pragma unroll
        for (int j = 0; j < 4; j++)
#pragma unroll
            for (int k = 0; k < 4; k++) acc[i][j][k] = 0.f;

    // global load indices: 2 x (row, seg) per tile per thread
    const int r0 = tid >> 2, s0 = (tid & 3);
    const int r1 = (256 + tid) >> 2, s1 = s0;   // rows 64..127

    for (int kt = 0; kt < 32; kt++) {
        const int kg = kt * 32;
        if (kt) __syncthreads();
        {
            const size_t gA0 = (size_t)(m_blk + r0) * KK + kg + s0 * 8;
            const size_t gA1 = (size_t)(m_blk + r1) * KK + kg + s1 * 8;
            const size_t gB0 = (size_t)(n_blk + r0) * KK + kg + s0 * 8;
            const size_t gB1 = (size_t)(n_blk + r1) * KK + kg + s1 * 8;
            const int d0 = r0 * SROW + s0 * 8, d1 = r1 * SROW + s1 * 8;
            *(uint4*)&sAh[d0] = *(const uint4*)(Ah + gA0);
            *(uint4*)&sAh[d1] = *(const uint4*)(Ah + gA1);
            *(uint4*)&sAl[d0] = *(const uint4*)(Al + gA0);
            *(uint4*)&sAl[d1] = *(const uint4*)(Al + gA1);
            *(uint4*)&sBh[d0] = *(const uint4*)(Bh + gB0);
            *(uint4*)&sBh[d1] = *(const uint4*)(Bh + gB1);
            *(uint4*)&sBl[d0] = *(const uint4*)(Bl + gB0);
            *(uint4*)&sBl[d1] = *(const uint4*)(Bl + gB1);
        }
        __syncthreads();

#pragma unroll
        for (int ks = 0; ks < 2; ks++) {
            const uint32_t kb = ks * 32;   // 16 elems * 2B
            // B fragments: x4 gives 2 n-frags each; nip=0 -> n0..15, nip=1 -> n16..31
            uint32_t bh[2][4], bl[2][4];
#pragma unroll
            for (int nip = 0; nip < 2; nip++) {
                const uint32_t bo = b_off + (uint32_t)(nip * 16 * SROW) * 2 + kb;
                ldsm_x4(bh[nip], uBh + bo);
                ldsm_x4(bl[nip], uBl + bo);
            }
#pragma unroll
            for (int mi = 0; mi < 4; mi++) {
                const uint32_t ao = a_off + (uint32_t)(mi * 16 * SROW) * 2 + kb;
                uint32_t ah[4], al[4];
                ldsm_x4(ah, uAh + ao);
                ldsm_x4(al, uAl + ao);
#pragma unroll
                for (int ni = 0; ni < 4; ni++) {
                    const uint32_t b0h = bh[ni >> 1][(ni & 1) * 2];
                    const uint32_t b1h = bh[ni >> 1][(ni & 1) * 2 + 1];
                    const uint32_t b0l = bl[ni >> 1][(ni & 1) * 2];
                    const uint32_t b1l = bl[ni >> 1][(ni & 1) * 2 + 1];
                    mma16816(acc[mi][ni], ah, b0h, b1h);
                    mma16816(acc[mi][ni], ah, b0l, b1l);
                    mma16816(acc[mi][ni], al, b0h, b1h);
                }
            }
        }
    }

    // epilogue: fragment (mi,ni): lane t -> rows (t>>2, t>>2+8), cols (t&3)*2,+1
#pragma unroll
    for (int mi = 0; mi < 4; mi++) {
#pragma unroll
        for (int ni = 0; ni < 4; ni++) {
#pragma unroll
            for (int half = 0; half < 2; half++) {
                const int m = m_blk + wm * 64 + mi * 16 + (l >> 2) + half * 8;
                const int n = n_blk + wn * 32 + ni * 8 + (l & 3) * 2;
                float2 o;
                o.x = acc[mi][ni][half * 2 + 0] + bias[n + 0];
                o.y = acc[mi][ni][half * 2 + 1] + bias[n + 1];
                if (MODE == 0) {
                    *(float2*)&out[(size_t)m * NN + n] = o;
                } else {
                    const int b = m >> 11, s = m & 2047;
                    const int h = n >> 6, hd = n & 63;
                    *(float2*)&out[((((size_t)b * HH + h) * SS + s) * HDIM) + hd] = o;
                }
            }
        }
    }
}

// ---------------- fused flash attention (unchanged, validated R2) ----------------
#define LDA 68
#define SM_BYTES (4 * 64 * LDA * 4)

__global__ __launch_bounds__(256) void attn_kernel(const int* __restrict__ mask,
                                                   const float* __restrict__ cmw)
{
    extern __shared__ float sm[];
    float* QT = sm;
    float* KT = sm + 64 * LDA;
    float* Vs = sm + 2 * 64 * LDA;
    float* PT = sm + 3 * 64 * LDA;
    __shared__ float s_bias;

    const int tid = threadIdx.x;
    const int tx = tid & 15;
    const int ty = tid >> 4;
    const int qt = blockIdx.x;
    const int h  = blockIdx.y;
    const int b  = blockIdx.z;
    const int q0g = qt * 64;

    if (tid == 0) {
        float sum = 0.f;
        for (int i = 0; i < 9; i++) sum += cmw[i];
        s_bias = sum / 9.0f;
    }

    {
        const int ql = tid >> 2;
        const int k0 = (tid & 3) * 16;
        const float* qp = g_Q + ((((size_t)b * HH + h) * SS + q0g + ql) * HDIM) + k0;
#pragma unroll
        for (int c = 0; c < 4; c++) {
            float4 v = *(const float4*)(qp + c * 4);
            QT[(k0 + c * 4 + 0) * LDA + ql] = v.x;
            QT[(k0 + c * 4 + 1) * LDA + ql] = v.y;
            QT[(k0 + c * 4 + 2) * LDA + ql] = v.z;
            QT[(k0 + c * 4 + 3) * LDA + ql] = v.w;
        }
    }
    __syncthreads();
    const float mbias = s_bias;

    float m_st[4], l_st[4], acc[4][4];
#pragma unroll
    for (int i = 0; i < 4; i++) {
        m_st[i] = -INFINITY;
        l_st[i] = 0.f;
#pragma unroll
        for (int j = 0; j < 4; j++) acc[i][j] = 0.f;
    }

    const int rl = tid >> 2;
    const int c0 = (tid & 3) * 16;
    const float* kbase = g_K + ((((size_t)b * HH + h) * SS) * HDIM);
    const float* vbase = g_V + ((((size_t)b * HH + h) * SS) * HDIM);

    for (int jt = 0; jt < 32; jt++) {
        const int j0g = jt * 64;
        float4 kv[4], vv[4];
        const float* kp = kbase + (size_t)(j0g + rl) * HDIM + c0;
        const float* vp = vbase + (size_t)(j0g + rl) * HDIM + c0;
#pragma unroll
        for (int c = 0; c < 4; c++) {
            kv[c] = *(const float4*)(kp + c * 4);
            vv[c] = *(const float4*)(vp + c * 4);
        }
        int4 mv[4];
#pragma unroll
        for (int qi = 0; qi < 4; qi++) {
            mv[qi] = *(const int4*)&mask[((size_t)b * SS + (q0g + ty * 4 + qi)) * SS
                                         + j0g + tx * 4];
        }

        __syncthreads();
#pragma unroll
        for (int c = 0; c < 4; c++) {
            KT[(c0 + c * 4 + 0) * LDA + rl] = kv[c].x;
            KT[(c0 + c * 4 + 1) * LDA + rl] = kv[c].y;
            KT[(c0 + c * 4 + 2) * LDA + rl] = kv[c].z;
            KT[(c0 + c * 4 + 3) * LDA + rl] = kv[c].w;
            *(float4*)&Vs[rl * LDA + c0 + c * 4] = vv[c];
        }
        __syncthreads();

        float sc[4][4];
#pragma unroll
        for (int i = 0; i < 4; i++)
#pragma unroll
            for (int j = 0; j < 4; j++) sc[i][j] = 0.f;

#pragma unroll 8
        for (int k = 0; k < 64; k++) {
            float4 qv = *(float4*)&QT[k * LDA + ty * 4];
            float4 kw = *(float4*)&KT[k * LDA + tx * 4];
            float qa[4] = {qv.x, qv.y, qv.z, qv.w};
            float ka[4] = {kw.x, kw.y, kw.z, kw.w};
#pragma unroll
            for (int i = 0; i < 4; i++)
#pragma unroll
                for (int j = 0; j < 4; j++)
                    sc[i][j] = fmaf(qa[i], ka[j], sc[i][j]);
        }

#pragma unroll
        for (int qi = 0; qi < 4; qi++) {
            const int mm[4] = {mv[qi].x, mv[qi].y, mv[qi].z, mv[qi].w};
#pragma unroll
            for (int ji = 0; ji < 4; ji++) {
                float v = sc[qi][ji] * 0.125f + mbias;
                sc[qi][ji] = (mm[ji] == 0) ? -1e9f : v;
            }
        }

#pragma unroll
        for (int qi = 0; qi < 4; qi++) {
            float rmax = fmaxf(fmaxf(sc[qi][0], sc[qi][1]), fmaxf(sc[qi][2], sc[qi][3]));
#pragma unroll
            for (int off = 1; off < 16; off <<= 1)
                rmax = fmaxf(rmax, __shfl_xor_sync(0xffffffffu, rmax, off));
            const float m_new = fmaxf(m_st[qi], rmax);
            const float corr = __expf(m_st[qi] - m_new);
            m_st[qi] = m_new;
            float rsum = 0.f;
#pragma unroll
            for (int ji = 0; ji < 4; ji++) {
                const float p = __expf(sc[qi][ji] - m_new);
                sc[qi][ji] = p;
                rsum += p;
            }
#pragma unroll
            for (int off = 1; off < 16; off <<= 1)
                rsum += __shfl_xor_sync(0xffffffffu, rsum, off);
            l_st[qi] = l_st[qi] * corr + rsum;
#pragma unroll
            for (int di = 0; di < 4; di++) acc[qi][di] *= corr;
#pragma unroll
            for (int ji = 0; ji < 4; ji++)
                PT[(tx * 4 + ji) * LDA + ty * 4 + qi] = sc[qi][ji];
        }
        __syncthreads();

#pragma unroll 8
        for (int j = 0; j < 64; j++) {
            float4 pv = *(float4*)&PT[j * LDA + ty * 4];
            float4 vw = *(float4*)&Vs[j * LDA + tx * 4];
            float pa[4] = {pv.x, pv.y, pv.z, pv.w};
            float va[4] = {vw.x, vw.y, vw.z, vw.w};
#pragma unroll
            for (int i = 0; i < 4; i++)
#pragma unroll
                for (int d = 0; d < 4; d++)
                    acc[i][d] = fmaf(pa[i], va[d], acc[i][d]);
        }
    }

#pragma unroll
    for (int qi = 0; qi < 4; qi++) {
        const float inv = 1.0f / l_st[qi];
        const int qg = q0g + ty * 4 + qi;
        float4 r;
        r.x = acc[qi][0] * inv;
        r.y = acc[qi][1] * inv;
        r.z = acc[qi][2] * inv;
        r.w = acc[qi][3] * inv;
        *(float4*)&g_ctx[((size_t)b * SS + qg) * DD + h * HDIM + tx * 4] = r;
    }
}

// ---------------- launch ----------------
extern "C" void kernel_launch(void* const* d_in, const int* in_sizes, int n_in,
                              void* d_out, int out_size)
{
    const float* x   = (const float*)d_in[0];
    const float* Wq  = (const float*)d_in[1];
    const float* bq  = (const float*)d_in[2];
    const float* Wk  = (const float*)d_in[3];
    const float* bk  = (const float*)d_in[4];
    const float* Wv  = (const float*)d_in[5];
    const float* bv  = (const float*)d_in[6];
    const float* Wo  = (const float*)d_in[7];
    const float* bo  = (const float*)d_in[8];
    const float* cmw = (const float*)d_in[9];
    const int*  mask = (const int*)d_in[10];
    float* out = (float*)d_out;

    void *pQ, *pK, *pV, *pC, *pAh, *pAl, *pWh, *pWl;
    cudaGetSymbolAddress(&pQ, g_Q);
    cudaGetSymbolAddress(&pK, g_K);
    cudaGetSymbolAddress(&pV, g_V);
    cudaGetSymbolAddress(&pC, g_ctx);
    cudaGetSymbolAddress(&pAh, g_Ah);
    cudaGetSymbolAddress(&pAl, g_Al);
    cudaGetSymbolAddress(&pWh, g_Wth);
    cudaGetSymbolAddress(&pWl, g_Wtl);
    __nv_bfloat16* Ahp = (__nv_bfloat16*)pAh;
    __nv_bfloat16* Alp = (__nv_bfloat16*)pAl;
    __nv_bfloat16* Whp = (__nv_bfloat16*)pWh;
    __nv_bfloat16* Wlp = (__nv_bfloat16*)pWl;

    static int s_init = 0;
    if (!s_init) {
        cudaFuncSetAttribute(attn_kernel, cudaFuncAttributeMaxDynamicSharedMemorySize, SM_BYTES);
        s_init = 1;
    }

    const dim3 gg(NN / 128, MTOT / 128);   // 8 x 32
    const dim3 gw(NN / 32, KK / 32);       // 32 x 32
    const dim3 bw(32, 8);

    // x -> bf16 hi/lo
    convx_kernel<<<(MTOT * KK) / (256 * 4), 256>>>((const float4*)x, Ahp, Alp);

    convW_kernel<<<gw, bw>>>(Wq, Whp, Wlp);
    gemm_mma_kernel<1><<<gg, 256>>>(Ahp, Alp, Whp, Wlp, bq, (float*)pQ);
    convW_kernel<<<gw, bw>>>(Wk, Whp, Wlp);
    gemm_mma_kernel<1><<<gg, 256>>>(Ahp, Alp, Whp, Wlp, bk, (float*)pK);
    convW_kernel<<<gw, bw>>>(Wv, Whp, Wlp);
    gemm_mma_kernel<1><<<gg, 256>>>(Ahp, Alp, Whp, Wlp, bv, (float*)pV);

    attn_kernel<<<dim3(SS / 64, HH, BB), 256, SM_BYTES>>>(mask, cmw);

    // ctx -> bf16 hi/lo, out-projection
    convx_kernel<<<(MTOT * DD) / (256 * 4), 256>>>((const float4*)pC, Ahp, Alp);
    convW_kernel<<<gw, bw>>>(Wo, Whp, Wlp);
    gemm_mma_kernel<0><<<gg, 256>>>(Ahp, Alp, Whp, Wlp, bo, out);
}

// round 5
// speedup vs baseline: 1.7035x; 1.2513x over previous
#include <cuda_runtime.h>
#include <cuda_bf16.h>
#include <cstdint>
#include <math.h>

#define BB 2
#define SS 2048
#define DD 1024
#define HH 16
#define HDIM 64
#define MTOT (BB*SS)      // 4096
#define NN 1024
#define KK 1024

// ---------------- scratch ----------------
__device__ __nv_bfloat16 g_Qh[(size_t)BB*HH*SS*HDIM];
__device__ __nv_bfloat16 g_Ql[(size_t)BB*HH*SS*HDIM];
__device__ __nv_bfloat16 g_Kh[(size_t)BB*HH*SS*HDIM];
__device__ __nv_bfloat16 g_Kl[(size_t)BB*HH*SS*HDIM];
__device__ __nv_bfloat16 g_Vh[(size_t)BB*HH*SS*HDIM];
__device__ __nv_bfloat16 g_Vl[(size_t)BB*HH*SS*HDIM];
__device__ __nv_bfloat16 g_Ah[(size_t)MTOT*KK];
__device__ __nv_bfloat16 g_Al[(size_t)MTOT*KK];
__device__ __nv_bfloat16 g_Wth[(size_t)NN*KK];   // W^T hi  [n][k]
__device__ __nv_bfloat16 g_Wtl[(size_t)NN*KK];   // W^T lo
__device__ char g_mask8[(size_t)BB*SS*SS];

__device__ __forceinline__ uint32_t smem_u32(const void* p) {
    uint32_t a;
    asm("{ .reg .u64 t; cvta.to.shared.u64 t, %1; cvt.u32.u64 %0, t; }" : "=r"(a) : "l"(p));
    return a;
}
__device__ __forceinline__ void ldsm_x4(uint32_t* r, uint32_t addr) {
    asm volatile("ldmatrix.sync.aligned.m8n8.x4.shared.b16 {%0,%1,%2,%3}, [%4];"
                 : "=r"(r[0]), "=r"(r[1]), "=r"(r[2]), "=r"(r[3]) : "r"(addr));
}
__device__ __forceinline__ void ldsm_x4_t(uint32_t* r, uint32_t addr) {
    asm volatile("ldmatrix.sync.aligned.m8n8.x4.trans.shared.b16 {%0,%1,%2,%3}, [%4];"
                 : "=r"(r[0]), "=r"(r[1]), "=r"(r[2]), "=r"(r[3]) : "r"(addr));
}
__device__ __forceinline__ void mma16816(float* c, const uint32_t* a, uint32_t b0, uint32_t b1) {
    asm volatile("mma.sync.aligned.m16n8k16.row.col.f32.bf16.bf16.f32 "
                 "{%0,%1,%2,%3}, {%4,%5,%6,%7}, {%8,%9}, {%0,%1,%2,%3};"
                 : "+f"(c[0]), "+f"(c[1]), "+f"(c[2]), "+f"(c[3])
                 : "r"(a[0]), "r"(a[1]), "r"(a[2]), "r"(a[3]), "r"(b0), "r"(b1));
}
__device__ __forceinline__ uint32_t pack_bf16(float lo, float hi) {
    uint32_t r;
    asm("cvt.rn.bf16x2.f32 %0, %1, %2;" : "=r"(r) : "f"(hi), "f"(lo));
    return r;
}
__device__ __forceinline__ float bf16lo_f(uint32_t p) { return __int_as_float(p << 16); }
__device__ __forceinline__ float bf16hi_f(uint32_t p) { return __int_as_float(p & 0xffff0000u); }

// fast exp: exp2 poly on FMA pipe (~8 ops). Valid for x <= 0 (clamped at -87).
__device__ __forceinline__ float fexp(float x) {
    x = fmaxf(x, -87.0f);
    float t = fmaf(x, 1.4426950408889634f, 12582912.0f);
    int n = __float_as_int(t) - 0x4b400000;
    float nf = t - 12582912.0f;
    float f = fmaf(x, 1.4426950408889634f, -nf);
    float p = 0.0013333558f;
    p = fmaf(p, f, 0.0096181298f);
    p = fmaf(p, f, 0.0555041087f);
    p = fmaf(p, f, 0.2402265070f);
    p = fmaf(p, f, 0.6931471806f);
    p = fmaf(p, f, 1.0f);
    return p * __int_as_float((n + 127) << 23);
}

// ================= prep kernels =================
__global__ __launch_bounds__(256) void convx_kernel(const float4* __restrict__ X,
                                                    __nv_bfloat16* __restrict__ H,
                                                    __nv_bfloat16* __restrict__ L)
{
    size_t i = (size_t)blockIdx.x * 256 + threadIdx.x;
    float4 v = X[i];
    __nv_bfloat16 h0 = __float2bfloat16(v.x);
    __nv_bfloat16 h1 = __float2bfloat16(v.y);
    __nv_bfloat16 h2 = __float2bfloat16(v.z);
    __nv_bfloat16 h3 = __float2bfloat16(v.w);
    __nv_bfloat162* H2 = (__nv_bfloat162*)H;
    __nv_bfloat162* L2 = (__nv_bfloat162*)L;
    H2[2*i]   = __nv_bfloat162(h0, h1);
    H2[2*i+1] = __nv_bfloat162(h2, h3);
    L2[2*i]   = __nv_bfloat162(__float2bfloat16(v.x - __bfloat162float(h0)),
                               __float2bfloat16(v.y - __bfloat162float(h1)));
    L2[2*i+1] = __nv_bfloat162(__float2bfloat16(v.z - __bfloat162float(h2)),
                               __float2bfloat16(v.w - __bfloat162float(h3)));
}

__global__ __launch_bounds__(256) void convW_kernel(const float* __restrict__ W,
                                                    __nv_bfloat16* __restrict__ Th,
                                                    __nv_bfloat16* __restrict__ Tl)
{
    __shared__ float t[32][33];
    const int n0 = blockIdx.x * 32, k0 = blockIdx.y * 32;
    const int tx = threadIdx.x, ty = threadIdx.y;
#pragma unroll
    for (int r = 0; r < 4; r++)
        t[ty + 8*r][tx] = W[(size_t)(k0 + ty + 8*r) * NN + n0 + tx];
    __syncthreads();
#pragma unroll
    for (int r = 0; r < 4; r++) {
        float v = t[tx][ty + 8*r];
        __nv_bfloat16 h = __float2bfloat16(v);
        size_t o = (size_t)(n0 + ty + 8*r) * KK + k0 + tx;
        Th[o] = h;
        Tl[o] = __float2bfloat16(v - __bfloat162float(h));
    }
}

__global__ __launch_bounds__(256) void mask8_kernel(const int4* __restrict__ m,
                                                    uint32_t* __restrict__ o)
{
    size_t i = (size_t)blockIdx.x * 256 + threadIdx.x;
    int4 v = m[i];
    uint32_t r = (v.x ? 1u : 0u) | (v.y ? 0x100u : 0u) | (v.z ? 0x10000u : 0u) | (v.w ? 0x1000000u : 0u);
    o[i] = r;
}

// ================= mma.sync bf16-split GEMM =================
// MODE 0: fp32 out row-major. MODE 1: bf16 hi/lo split, scaled 1/8, QKV scatter.
// MODE 2: bf16 hi/lo split, QKV scatter.
#define SROW 40

template<int MODE>
__global__ __launch_bounds__(256, 2) void gemm_mma_kernel(
    const __nv_bfloat16* __restrict__ Ah, const __nv_bfloat16* __restrict__ Al,
    const __nv_bfloat16* __restrict__ Bh, const __nv_bfloat16* __restrict__ Bl,
    const float* __restrict__ bias, float* __restrict__ out,
    __nv_bfloat16* __restrict__ outH, __nv_bfloat16* __restrict__ outL)
{
    __shared__ __nv_bfloat16 sAh[128 * SROW];
    __shared__ __nv_bfloat16 sAl[128 * SROW];
    __shared__ __nv_bfloat16 sBh[128 * SROW];
    __shared__ __nv_bfloat16 sBl[128 * SROW];

    const int tid = threadIdx.x;
    const int wid = tid >> 5;
    const int l   = tid & 31;
    const int wm  = wid >> 2;
    const int wn  = wid & 3;
    const int m_blk = blockIdx.y * 128;
    const int n_blk = blockIdx.x * 128;

    const uint32_t uAh = smem_u32(sAh);
    const uint32_t uAl = smem_u32(sAl);
    const uint32_t uBh = smem_u32(sBh);
    const uint32_t uBl = smem_u32(sBl);

    const uint32_t a_off = (uint32_t)((wm * 64 + (l & 15)) * SROW + (l >> 4) * 8) * 2;
    const uint32_t b_off = (uint32_t)((wn * 32 + (l & 7) + ((l >> 4) << 3)) * SROW
                                      + ((l >> 3) & 1) * 8) * 2;

    float acc[4][4][4];
#pragma unroll
    for (int i = 0; i < 4; i++)
#pragma unroll
        for (int j = 0; j < 4; j++)
#pragma unroll
            for (int k = 0; k < 4; k++) acc[i][j][k] = 0.f;

    const int r0 = tid >> 2, s0 = (tid & 3);
    const int r1 = (256 + tid) >> 2, s1 = s0;

    for (int kt = 0; kt < 32; kt++) {
        const int kg = kt * 32;
        if (kt) __syncthreads();
        {
            const size_t gA0 = (size_t)(m_blk + r0) * KK + kg + s0 * 8;
            const size_t gA1 = (size_t)(m_blk + r1) * KK + kg + s1 * 8;
            const size_t gB0 = (size_t)(n_blk + r0) * KK + kg + s0 * 8;
            const size_t gB1 = (size_t)(n_blk + r1) * KK + kg + s1 * 8;
            const int d0 = r0 * SROW + s0 * 8, d1 = r1 * SROW + s1 * 8;
            *(uint4*)&sAh[d0] = *(const uint4*)(Ah + gA0);
            *(uint4*)&sAh[d1] = *(const uint4*)(Ah + gA1);
            *(uint4*)&sAl[d0] = *(const uint4*)(Al + gA0);
            *(uint4*)&sAl[d1] = *(const uint4*)(Al + gA1);
            *(uint4*)&sBh[d0] = *(const uint4*)(Bh + gB0);
            *(uint4*)&sBh[d1] = *(const uint4*)(Bh + gB1);
            *(uint4*)&sBl[d0] = *(const uint4*)(Bl + gB0);
            *(uint4*)&sBl[d1] = *(const uint4*)(Bl + gB1);
        }
        __syncthreads();

#pragma unroll
        for (int ks = 0; ks < 2; ks++) {
            const uint32_t kb = ks * 32;
            uint32_t bh[2][4], bl[2][4];
#pragma unroll
            for (int nip = 0; nip < 2; nip++) {
                const uint32_t bo = b_off + (uint32_t)(nip * 16 * SROW) * 2 + kb;
                ldsm_x4(bh[nip], uBh + bo);
                ldsm_x4(bl[nip], uBl + bo);
            }
#pragma unroll
            for (int mi = 0; mi < 4; mi++) {
                const uint32_t ao = a_off + (uint32_t)(mi * 16 * SROW) * 2 + kb;
                uint32_t ah[4], al[4];
                ldsm_x4(ah, uAh + ao);
                ldsm_x4(al, uAl + ao);
#pragma unroll
                for (int ni = 0; ni < 4; ni++) {
                    const uint32_t b0h = bh[ni >> 1][(ni & 1) * 2];
                    const uint32_t b1h = bh[ni >> 1][(ni & 1) * 2 + 1];
                    const uint32_t b0l = bl[ni >> 1][(ni & 1) * 2];
                    const uint32_t b1l = bl[ni >> 1][(ni & 1) * 2 + 1];
                    mma16816(acc[mi][ni], ah, b0h, b1h);
                    mma16816(acc[mi][ni], ah, b0l, b1l);
                    mma16816(acc[mi][ni], al, b0h, b1h);
                }
            }
        }
    }

#pragma unroll
    for (int mi = 0; mi < 4; mi++) {
#pragma unroll
        for (int ni = 0; ni < 4; ni++) {
#pragma unroll
            for (int half = 0; half < 2; half++) {
                const int m = m_blk + wm * 64 + mi * 16 + (l >> 2) + half * 8;
                const int n = n_blk + wn * 32 + ni * 8 + (l & 3) * 2;
                float vx = acc[mi][ni][half * 2 + 0] + bias[n + 0];
                float vy = acc[mi][ni][half * 2 + 1] + bias[n + 1];
                if (MODE == 0) {
                    *(float2*)&out[(size_t)m * NN + n] = make_float2(vx, vy);
                } else {
                    if (MODE == 1) { vx *= 0.125f; vy *= 0.125f; }
                    const int b = m >> 11, s = m & 2047;
                    const int h = n >> 6, hd = n & 63;
                    const size_t o = ((((size_t)b * HH + h) * SS + s) * HDIM) + hd;
                    __nv_bfloat16 hx = __float2bfloat16(vx);
                    __nv_bfloat16 hy = __float2bfloat16(vy);
                    *(__nv_bfloat162*)&outH[o] = __nv_bfloat162(hx, hy);
                    *(__nv_bfloat162*)&outL[o] = __nv_bfloat162(
                        __float2bfloat16(vx - __bfloat162float(hx)),
                        __float2bfloat16(vy - __bfloat162float(hy)));
                }
            }
        }
    }
}

// ================= mma.sync flash attention =================
// CTA: 128 q rows, 8 warps x 16 rows. 16 key tiles of 128.
#define SRA 72
#define ATT_SMEM 110592

__global__ __launch_bounds__(256) void attn_mma_kernel(
    const char* __restrict__ mask8, const float* __restrict__ cmw,
    const __nv_bfloat16* __restrict__ Qh, const __nv_bfloat16* __restrict__ Ql,
    const __nv_bfloat16* __restrict__ Kh, const __nv_bfloat16* __restrict__ Kl,
    const __nv_bfloat16* __restrict__ Vh, const __nv_bfloat16* __restrict__ Vl,
    __nv_bfloat16* __restrict__ Oh, __nv_bfloat16* __restrict__ Ol)
{
    extern __shared__ char smn[];
    __nv_bfloat16* sQh = (__nv_bfloat16*)smn;
    __nv_bfloat16* sQl = (__nv_bfloat16*)(smn + 18432);
    char* sMask = smn;                               // overlays sQh after Q consumed
    __nv_bfloat16* sKh = (__nv_bfloat16*)(smn + 36864);
    __nv_bfloat16* sKl = (__nv_bfloat16*)(smn + 55296);
    __nv_bfloat16* sVh = (__nv_bfloat16*)(smn + 73728);
    __nv_bfloat16* sVl = (__nv_bfloat16*)(smn + 92160);
    __shared__ float s_bias;

    const int tid = threadIdx.x, wid = tid >> 5, l = tid & 31;
    const int q0 = blockIdx.x * 128, h = blockIdx.y, b = blockIdx.z;

    if (tid == 0) {
        float s = 0.f;
        for (int i = 0; i < 9; i++) s += cmw[i];
        s_bias = s / 9.0f;
    }

    const size_t qkvb = ((size_t)(b * HH + h) * SS) * HDIM;

    // Q tiles -> smem
#pragma unroll
    for (int it = 0; it < 4; it++) {
        int idx = it * 256 + tid;
        int r = idx >> 3, sg = idx & 7;
        size_t g = qkvb + (size_t)(q0 + r) * HDIM + sg * 8;
        int d = r * SRA + sg * 8;
        *(uint4*)&sQh[d] = *(const uint4*)&Qh[g];
        *(uint4*)&sQl[d] = *(const uint4*)&Ql[g];
    }
    __syncthreads();

    const uint32_t uQh = smem_u32(sQh), uQl = smem_u32(sQl);
    uint32_t qfh[4][4], qfl[4][4];
    const uint32_t qoff = (uint32_t)((wid * 16 + (l & 15)) * SRA + (l >> 4) * 8) * 2;
#pragma unroll
    for (int kc = 0; kc < 4; kc++) {
        ldsm_x4(qfh[kc], uQh + qoff + kc * 32);
        ldsm_x4(qfl[kc], uQl + qoff + kc * 32);
    }
    __syncthreads();   // Q regs consumed; mask may overlay Q smem now
    const float mbias = s_bias;

    const uint32_t uKh = smem_u32(sKh), uKl = smem_u32(sKl);
    const uint32_t uVh = smem_u32(sVh), uVl = smem_u32(sVl);

    float mx0 = -1e30f, mx1 = -1e30f, sum0 = 0.f, sum1 = 0.f;
    float acc[8][4];
#pragma unroll
    for (int i = 0; i < 8; i++)
#pragma unroll
        for (int j = 0; j < 4; j++) acc[i][j] = 0.f;

    const uint32_t koff = (uint32_t)(((l & 7) + ((l >> 4) << 3)) * SRA + ((l >> 3) & 1) * 8) * 2;
    const uint32_t voff = (uint32_t)((l & 15) * SRA + (l >> 4) * 8) * 2;
    const int rl0 = wid * 16 + (l >> 2);        // CTA-local q rows
    const int rl1 = rl0 + 8;

    for (int jt = 0; jt < 16; jt++) {
        const int j0 = jt * 128;
        if (jt) __syncthreads();
#pragma unroll
        for (int it = 0; it < 4; it++) {
            int idx = it * 256 + tid;
            int r = idx >> 3, sg = idx & 7;
            size_t g = qkvb + (size_t)(j0 + r) * HDIM + sg * 8;
            int d = r * SRA + sg * 8;
            *(uint4*)&sKh[d] = *(const uint4*)&Kh[g];
            *(uint4*)&sKl[d] = *(const uint4*)&Kl[g];
            *(uint4*)&sVh[d] = *(const uint4*)&Vh[g];
            *(uint4*)&sVl[d] = *(const uint4*)&Vl[g];
        }
#pragma unroll
        for (int it = 0; it < 4; it++) {
            int idx = it * 256 + tid;
            int r = idx >> 3, c = (idx & 7) * 16;
            uint4 v = *(const uint4*)&mask8[((size_t)b * SS + q0 + r) * SS + j0 + c];
            *(uint4*)&sMask[r * 144 + c] = v;
        }
        __syncthreads();

        // ---- scores = Qs . K^T (3-product split) ----
        float sc[16][4];
#pragma unroll
        for (int i = 0; i < 16; i++)
#pragma unroll
            for (int j = 0; j < 4; j++) sc[i][j] = 0.f;

#pragma unroll
        for (int kc = 0; kc < 4; kc++) {
#pragma unroll
            for (int nb = 0; nb < 8; nb++) {
                uint32_t bh[4], bl[4];
                uint32_t bo = koff + (uint32_t)(nb * 16 * SRA) * 2 + kc * 32;
                ldsm_x4(bh, uKh + bo);
                ldsm_x4(bl, uKl + bo);
                mma16816(sc[2*nb],   qfh[kc], bh[0], bh[1]);
                mma16816(sc[2*nb],   qfh[kc], bl[0], bl[1]);
                mma16816(sc[2*nb],   qfl[kc], bh[0], bh[1]);
                mma16816(sc[2*nb+1], qfh[kc], bh[2], bh[3]);
                mma16816(sc[2*nb+1], qfh[kc], bl[2], bl[3]);
                mma16816(sc[2*nb+1], qfl[kc], bh[2], bh[3]);
            }
        }

        // ---- bias + mask + online softmax ----
        float rm0 = -1e30f, rm1 = -1e30f;
#pragma unroll
        for (int nf = 0; nf < 16; nf++) {
            int c = nf * 8 + (l & 3) * 2;
            char2 ma = *(char2*)&sMask[rl0 * 144 + c];
            char2 mb = *(char2*)&sMask[rl1 * 144 + c];
            float v0 = sc[nf][0] + mbias;
            float v1 = sc[nf][1] + mbias;
            float v2 = sc[nf][2] + mbias;
            float v3 = sc[nf][3] + mbias;
            sc[nf][0] = ma.x ? v0 : -1e9f;
            sc[nf][1] = ma.y ? v1 : -1e9f;
            sc[nf][2] = mb.x ? v2 : -1e9f;
            sc[nf][3] = mb.y ? v3 : -1e9f;
            rm0 = fmaxf(rm0, fmaxf(sc[nf][0], sc[nf][1]));
            rm1 = fmaxf(rm1, fmaxf(sc[nf][2], sc[nf][3]));
        }
        rm0 = fmaxf(rm0, __shfl_xor_sync(0xffffffffu, rm0, 1));
        rm0 = fmaxf(rm0, __shfl_xor_sync(0xffffffffu, rm0, 2));
        rm1 = fmaxf(rm1, __shfl_xor_sync(0xffffffffu, rm1, 1));
        rm1 = fmaxf(rm1, __shfl_xor_sync(0xffffffffu, rm1, 2));

        float mn0 = fmaxf(mx0, rm0), mn1 = fmaxf(mx1, rm1);
        float corr0 = fexp(mx0 - mn0), corr1 = fexp(mx1 - mn1);
        mx0 = mn0; mx1 = mn1;

        float rs0 = 0.f, rs1 = 0.f;
#pragma unroll
        for (int nf = 0; nf < 16; nf++) {
            float p0 = fexp(sc[nf][0] - mn0);
            float p1 = fexp(sc[nf][1] - mn0);
            float p2 = fexp(sc[nf][2] - mn1);
            float p3 = fexp(sc[nf][3] - mn1);
            sc[nf][0] = p0; sc[nf][1] = p1; sc[nf][2] = p2; sc[nf][3] = p3;
            rs0 += p0 + p1;
            rs1 += p2 + p3;
        }
        rs0 += __shfl_xor_sync(0xffffffffu, rs0, 1);
        rs0 += __shfl_xor_sync(0xffffffffu, rs0, 2);
        rs1 += __shfl_xor_sync(0xffffffffu, rs1, 1);
        rs1 += __shfl_xor_sync(0xffffffffu, rs1, 2);
        sum0 = sum0 * corr0 + rs0;
        sum1 = sum1 * corr1 + rs1;
#pragma unroll
        for (int nf = 0; nf < 8; nf++) {
            acc[nf][0] *= corr0; acc[nf][1] *= corr0;
            acc[nf][2] *= corr1; acc[nf][3] *= corr1;
        }

        // ---- ctx += P . V (3-product split) ----
#pragma unroll
        for (int kc = 0; kc < 8; kc++) {
            uint32_t ah[4], al[4];
            {
                uint32_t t0 = pack_bf16(sc[2*kc][0], sc[2*kc][1]);
                uint32_t t1 = pack_bf16(sc[2*kc][2], sc[2*kc][3]);
                uint32_t t2 = pack_bf16(sc[2*kc+1][0], sc[2*kc+1][1]);
                uint32_t t3 = pack_bf16(sc[2*kc+1][2], sc[2*kc+1][3]);
                ah[0] = t0; ah[1] = t1; ah[2] = t2; ah[3] = t3;
                al[0] = pack_bf16(sc[2*kc][0] - bf16lo_f(t0),   sc[2*kc][1] - bf16hi_f(t0));
                al[1] = pack_bf16(sc[2*kc][2] - bf16lo_f(t1),   sc[2*kc][3] - bf16hi_f(t1));
                al[2] = pack_bf16(sc[2*kc+1][0] - bf16lo_f(t2), sc[2*kc+1][1] - bf16hi_f(t2));
                al[3] = pack_bf16(sc[2*kc+1][2] - bf16lo_f(t3), sc[2*kc+1][3] - bf16hi_f(t3));
            }
            const uint32_t vb = voff + (uint32_t)(kc * 16 * SRA) * 2;
#pragma unroll
            for (int db = 0; db < 4; db++) {
                uint32_t vh[4], vl[4];
                uint32_t vo = vb + db * 32;
                ldsm_x4_t(vh, uVh + vo);
                ldsm_x4_t(vl, uVl + vo);
                mma16816(acc[2*db],   ah, vh[0], vh[1]);
                mma16816(acc[2*db],   ah, vl[0], vl[1]);
                mma16816(acc[2*db],   al, vh[0], vh[1]);
                mma16816(acc[2*db+1], ah, vh[2], vh[3]);
                mma16816(acc[2*db+1], ah, vl[2], vl[3]);
                mma16816(acc[2*db+1], al, vh[2], vh[3]);
            }
        }
    }

    // ---- epilogue: ctx normalized, write bf16 hi/lo for final GEMM ----
    const float inv0 = 1.0f / sum0, inv1 = 1.0f / sum1;
    const size_t rg0 = (size_t)b * SS + q0 + wid * 16 + (l >> 2);
    const size_t rg1 = rg0 + 8;
#pragma unroll
    for (int nf = 0; nf < 8; nf++) {
        const int col = h * 64 + nf * 8 + (l & 3) * 2;
        float c0 = acc[nf][0] * inv0, c1 = acc[nf][1] * inv0;
        float c2 = acc[nf][2] * inv1, c3 = acc[nf][3] * inv1;
        __nv_bfloat16 h0 = __float2bfloat16(c0), h1 = __float2bfloat16(c1);
        __nv_bfloat16 h2 = __float2bfloat16(c2), h3 = __float2bfloat16(c3);
        *(__nv_bfloat162*)&Oh[rg0 * DD + col] = __nv_bfloat162(h0, h1);
        *(__nv_bfloat162*)&Ol[rg0 * DD + col] = __nv_bfloat162(
            __float2bfloat16(c0 - __bfloat162float(h0)),
            __float2bfloat16(c1 - __bfloat162float(h1)));
        *(__nv_bfloat162*)&Oh[rg1 * DD + col] = __nv_bfloat162(h2, h3);
        *(__nv_bfloat162*)&Ol[rg1 * DD + col] = __nv_bfloat162(
            __float2bfloat16(c2 - __bfloat162float(h2)),
            __float2bfloat16(c3 - __bfloat162float(h3)));
    }
}

// ---------------- launch ----------------
extern "C" void kernel_launch(void* const* d_in, const int* in_sizes, int n_in,
                              void* d_out, int out_size)
{
    const float* x   = (const float*)d_in[0];
    const float* Wq  = (const float*)d_in[1];
    const float* bq  = (const float*)d_in[2];
    const float* Wk  = (const float*)d_in[3];
    const float* bk  = (const float*)d_in[4];
    const float* Wv  = (const float*)d_in[5];
    const float* bv  = (const float*)d_in[6];
    const float* Wo  = (const float*)d_in[7];
    const float* bo  = (const float*)d_in[8];
    const float* cmw = (const float*)d_in[9];
    const int*  mask = (const int*)d_in[10];
    float* out = (float*)d_out;

    void *pQh, *pQl, *pKh, *pKl, *pVh, *pVl, *pAh, *pAl, *pWh, *pWl, *pM8;
    cudaGetSymbolAddress(&pQh, g_Qh);  cudaGetSymbolAddress(&pQl, g_Ql);
    cudaGetSymbolAddress(&pKh, g_Kh);  cudaGetSymbolAddress(&pKl, g_Kl);
    cudaGetSymbolAddress(&pVh, g_Vh);  cudaGetSymbolAddress(&pVl, g_Vl);
    cudaGetSymbolAddress(&pAh, g_Ah);  cudaGetSymbolAddress(&pAl, g_Al);
    cudaGetSymbolAddress(&pWh, g_Wth); cudaGetSymbolAddress(&pWl, g_Wtl);
    cudaGetSymbolAddress(&pM8, g_mask8);
    __nv_bfloat16* Ahp = (__nv_bfloat16*)pAh;
    __nv_bfloat16* Alp = (__nv_bfloat16*)pAl;
    __nv_bfloat16* Whp = (__nv_bfloat16*)pWh;
    __nv_bfloat16* Wlp = (__nv_bfloat16*)pWl;

    static int s_init = 0;
    if (!s_init) {
        cudaFuncSetAttribute(attn_mma_kernel, cudaFuncAttributeMaxDynamicSharedMemorySize, ATT_SMEM);
        s_init = 1;
    }

    const dim3 gg(NN / 128, MTOT / 128);
    const dim3 gw(NN / 32, KK / 32);
    const dim3 bw(32, 8);

    mask8_kernel<<<(BB * SS * SS) / (4 * 256), 256>>>((const int4*)mask, (uint32_t*)pM8);
    convx_kernel<<<(MTOT * KK) / (256 * 4), 256>>>((const float4*)x, Ahp, Alp);

    convW_kernel<<<gw, bw>>>(Wq, Whp, Wlp);
    gemm_mma_kernel<1><<<gg, 256>>>(Ahp, Alp, Whp, Wlp, bq, nullptr,
                                    (__nv_bfloat16*)pQh, (__nv_bfloat16*)pQl);
    convW_kernel<<<gw, bw>>>(Wk, Whp, Wlp);
    gemm_mma_kernel<2><<<gg, 256>>>(Ahp, Alp, Whp, Wlp, bk, nullptr,
                                    (__nv_bfloat16*)pKh, (__nv_bfloat16*)pKl);
    convW_kernel<<<gw, bw>>>(Wv, Whp, Wlp);
    gemm_mma_kernel<2><<<gg, 256>>>(Ahp, Alp, Whp, Wlp, bv, nullptr,
                                    (__nv_bfloat16*)pVh, (__nv_bfloat16*)pVl);

    attn_mma_kernel<<<dim3(SS / 128, HH, BB), 256, ATT_SMEM>>>(
        (const char*)pM8, cmw,
        (const __nv_bfloat16*)pQh, (const __nv_bfloat16*)pQl,
        (const __nv_bfloat16*)pKh, (const __nv_bfloat16*)pKl,
        (const __nv_bfloat16*)pVh, (const __nv_bfloat16*)pVl,
        Ahp, Alp);

    convW_kernel<<<gw, bw>>>(Wo, Whp, Wlp);
    gemm_mma_kernel<0><<<gg, 256>>>(Ahp, Alp, Whp, Wlp, bo, out, nullptr, nullptr);
}

// round 6
// speedup vs baseline: 2.5902x; 1.5205x over previous
#include <cuda_runtime.h>
#include <cuda_bf16.h>
#include <cstdint>
#include <math.h>

#define BB 2
#define SS 2048
#define DD 1024
#define HH 16
#define HDIM 64
#define MTOT (BB*SS)      // 4096
#define NN 1024
#define KK 1024

// ---------------- scratch ----------------
__device__ __nv_bfloat16 g_Qh[(size_t)BB*HH*SS*HDIM];
__device__ __nv_bfloat16 g_Ql[(size_t)BB*HH*SS*HDIM];
__device__ __nv_bfloat16 g_Kh[(size_t)BB*HH*SS*HDIM];
__device__ __nv_bfloat16 g_Kl[(size_t)BB*HH*SS*HDIM];
__device__ __nv_bfloat16 g_Vh[(size_t)BB*HH*SS*HDIM];
__device__ __nv_bfloat16 g_Vl[(size_t)BB*HH*SS*HDIM];
__device__ __nv_bfloat16 g_Ah[(size_t)MTOT*KK];
__device__ __nv_bfloat16 g_Al[(size_t)MTOT*KK];
__device__ __nv_bfloat16 g_Wth[(size_t)NN*KK];   // W^T hi  [n][k]
__device__ __nv_bfloat16 g_Wtl[(size_t)NN*KK];   // W^T lo
__device__ char g_mask8[(size_t)BB*SS*SS];

__device__ __forceinline__ uint32_t smem_u32(const void* p) {
    uint32_t a;
    asm("{ .reg .u64 t; cvta.to.shared.u64 t, %1; cvt.u32.u64 %0, t; }" : "=r"(a) : "l"(p));
    return a;
}
__device__ __forceinline__ void ldsm_x4(uint32_t* r, uint32_t addr) {
    asm volatile("ldmatrix.sync.aligned.m8n8.x4.shared.b16 {%0,%1,%2,%3}, [%4];"
                 : "=r"(r[0]), "=r"(r[1]), "=r"(r[2]), "=r"(r[3]) : "r"(addr));
}
__device__ __forceinline__ void ldsm_x4_t(uint32_t* r, uint32_t addr) {
    asm volatile("ldmatrix.sync.aligned.m8n8.x4.trans.shared.b16 {%0,%1,%2,%3}, [%4];"
                 : "=r"(r[0]), "=r"(r[1]), "=r"(r[2]), "=r"(r[3]) : "r"(addr));
}
__device__ __forceinline__ void mma16816(float* c, const uint32_t* a, uint32_t b0, uint32_t b1) {
    asm volatile("mma.sync.aligned.m16n8k16.row.col.f32.bf16.bf16.f32 "
                 "{%0,%1,%2,%3}, {%4,%5,%6,%7}, {%8,%9}, {%0,%1,%2,%3};"
                 : "+f"(c[0]), "+f"(c[1]), "+f"(c[2]), "+f"(c[3])
                 : "r"(a[0]), "r"(a[1]), "r"(a[2]), "r"(a[3]), "r"(b0), "r"(b1));
}
__device__ __forceinline__ void cpa16(uint32_t s, const void* g) {
    asm volatile("cp.async.cg.shared.global [%0], [%1], 16;" :: "r"(s), "l"(g));
}
#define CPA_COMMIT() asm volatile("cp.async.commit_group;" ::: "memory")
#define CPA_WAIT1()  asm volatile("cp.async.wait_group 1;" ::: "memory")
#define CPA_WAIT0()  asm volatile("cp.async.wait_group 0;" ::: "memory")

__device__ __forceinline__ uint32_t pack_bf16(float lo, float hi) {
    uint32_t r;
    asm("cvt.rn.bf16x2.f32 %0, %1, %2;" : "=r"(r) : "f"(hi), "f"(lo));
    return r;
}
__device__ __forceinline__ float bf16lo_f(uint32_t p) { return __int_as_float(p << 16); }
__device__ __forceinline__ float bf16hi_f(uint32_t p) { return __int_as_float(p & 0xffff0000u); }

// fast exp: exp2 poly on FMA pipe. Valid for x <= 0 (clamped at -87).
__device__ __forceinline__ float fexp(float x) {
    x = fmaxf(x, -87.0f);
    float t = fmaf(x, 1.4426950408889634f, 12582912.0f);
    int n = __float_as_int(t) - 0x4b400000;
    float nf = t - 12582912.0f;
    float f = fmaf(x, 1.4426950408889634f, -nf);
    float p = 0.0013333558f;
    p = fmaf(p, f, 0.0096181298f);
    p = fmaf(p, f, 0.0555041087f);
    p = fmaf(p, f, 0.2402265070f);
    p = fmaf(p, f, 0.6931471806f);
    p = fmaf(p, f, 1.0f);
    return p * __int_as_float((n + 127) << 23);
}

// ================= prep kernels =================
__global__ __launch_bounds__(256) void convx_kernel(const float4* __restrict__ X,
                                                    __nv_bfloat16* __restrict__ H,
                                                    __nv_bfloat16* __restrict__ L)
{
    size_t i = (size_t)blockIdx.x * 256 + threadIdx.x;
    float4 v = X[i];
    __nv_bfloat16 h0 = __float2bfloat16(v.x);
    __nv_bfloat16 h1 = __float2bfloat16(v.y);
    __nv_bfloat16 h2 = __float2bfloat16(v.z);
    __nv_bfloat16 h3 = __float2bfloat16(v.w);
    __nv_bfloat162* H2 = (__nv_bfloat162*)H;
    __nv_bfloat162* L2 = (__nv_bfloat162*)L;
    H2[2*i]   = __nv_bfloat162(h0, h1);
    H2[2*i+1] = __nv_bfloat162(h2, h3);
    L2[2*i]   = __nv_bfloat162(__float2bfloat16(v.x - __bfloat162float(h0)),
                               __float2bfloat16(v.y - __bfloat162float(h1)));
    L2[2*i+1] = __nv_bfloat162(__float2bfloat16(v.z - __bfloat162float(h2)),
                               __float2bfloat16(v.w - __bfloat162float(h3)));
}

__global__ __launch_bounds__(256) void convW_kernel(const float* __restrict__ W,
                                                    __nv_bfloat16* __restrict__ Th,
                                                    __nv_bfloat16* __restrict__ Tl)
{
    __shared__ float t[32][33];
    const int n0 = blockIdx.x * 32, k0 = blockIdx.y * 32;
    const int tx = threadIdx.x, ty = threadIdx.y;
#pragma unroll
    for (int r = 0; r < 4; r++)
        t[ty + 8*r][tx] = W[(size_t)(k0 + ty + 8*r) * NN + n0 + tx];
    __syncthreads();
#pragma unroll
    for (int r = 0; r < 4; r++) {
        float v = t[tx][ty + 8*r];
        __nv_bfloat16 h = __float2bfloat16(v);
        size_t o = (size_t)(n0 + ty + 8*r) * KK + k0 + tx;
        Th[o] = h;
        Tl[o] = __float2bfloat16(v - __bfloat162float(h));
    }
}

__global__ __launch_bounds__(256) void mask8_kernel(const int4* __restrict__ m,
                                                    uint32_t* __restrict__ o)
{
    size_t i = (size_t)blockIdx.x * 256 + threadIdx.x;
    int4 v = m[i];
    uint32_t r = (v.x ? 1u : 0u) | (v.y ? 0x100u : 0u) | (v.z ? 0x10000u : 0u) | (v.w ? 0x1000000u : 0u);
    o[i] = r;
}

// ================= mma.sync bf16-split GEMM, 2-stage cp.async pipeline ==========
#define SROW 40
#define GT_ELEM (128 * SROW)        // elements per tile (5120)
#define GT_BYTES (GT_ELEM * 2)      // 10240
#define GSTAGE_BYTES (4 * GT_BYTES) // 40960
#define GSM_BYTES (2 * GSTAGE_BYTES)

template<int MODE>
__global__ __launch_bounds__(256, 2) void gemm_mma_kernel(
    const __nv_bfloat16* __restrict__ Ah, const __nv_bfloat16* __restrict__ Al,
    const __nv_bfloat16* __restrict__ Bh, const __nv_bfloat16* __restrict__ Bl,
    const float* __restrict__ bias, float* __restrict__ out,
    __nv_bfloat16* __restrict__ outH, __nv_bfloat16* __restrict__ outL)
{
    extern __shared__ char gsm[];
    const uint32_t u0 = smem_u32(gsm);

    const int tid = threadIdx.x;
    const int wid = tid >> 5;
    const int l   = tid & 31;
    const int wm  = wid >> 2;
    const int wn  = wid & 3;
    const int m_blk = blockIdx.y * 128;
    const int n_blk = blockIdx.x * 128;

    const uint32_t a_off = (uint32_t)((wm * 64 + (l & 15)) * SROW + (l >> 4) * 8) * 2;
    const uint32_t b_off = (uint32_t)((wn * 32 + (l & 7) + ((l >> 4) << 3)) * SROW
                                      + ((l >> 3) & 1) * 8) * 2;

    float acc[4][4][4];
#pragma unroll
    for (int i = 0; i < 4; i++)
#pragma unroll
        for (int j = 0; j < 4; j++)
#pragma unroll
            for (int k = 0; k < 4; k++) acc[i][j][k] = 0.f;

    const int r0 = tid >> 2, s0 = (tid & 3);
    const int r1 = r0 + 64;
    const uint32_t d0 = (uint32_t)(r0 * SROW + s0 * 8) * 2;
    const uint32_t d1 = (uint32_t)(r1 * SROW + s0 * 8) * 2;

    // stage loader: 8 x 16B cp.async
#define G_LOAD(ST, KT) do {                                                     \
        const int kg_ = (KT) * 32;                                              \
        const uint32_t sb_ = u0 + (ST) * GSTAGE_BYTES;                          \
        const size_t gA0_ = (size_t)(m_blk + r0) * KK + kg_ + s0 * 8;           \
        const size_t gA1_ = (size_t)(m_blk + r1) * KK + kg_ + s0 * 8;           \
        const size_t gB0_ = (size_t)(n_blk + r0) * KK + kg_ + s0 * 8;           \
        const size_t gB1_ = (size_t)(n_blk + r1) * KK + kg_ + s0 * 8;           \
        cpa16(sb_ + 0 * GT_BYTES + d0, Ah + gA0_);                              \
        cpa16(sb_ + 0 * GT_BYTES + d1, Ah + gA1_);                              \
        cpa16(sb_ + 1 * GT_BYTES + d0, Al + gA0_);                              \
        cpa16(sb_ + 1 * GT_BYTES + d1, Al + gA1_);                              \
        cpa16(sb_ + 2 * GT_BYTES + d0, Bh + gB0_);                              \
        cpa16(sb_ + 2 * GT_BYTES + d1, Bh + gB1_);                              \
        cpa16(sb_ + 3 * GT_BYTES + d0, Bl + gB0_);                              \
        cpa16(sb_ + 3 * GT_BYTES + d1, Bl + gB1_);                              \
    } while (0)

    G_LOAD(0, 0);
    CPA_COMMIT();

    for (int kt = 0; kt < 32; kt++) {
        if (kt + 1 < 32) {
            G_LOAD((kt + 1) & 1, kt + 1);
            CPA_COMMIT();
            CPA_WAIT1();
        } else {
            CPA_WAIT0();
        }
        __syncthreads();

        const uint32_t sb = u0 + (kt & 1) * GSTAGE_BYTES;
        const uint32_t uAh = sb, uAl = sb + GT_BYTES, uBh = sb + 2 * GT_BYTES, uBl = sb + 3 * GT_BYTES;

#pragma unroll
        for (int ks = 0; ks < 2; ks++) {
            const uint32_t kb = ks * 32;
            uint32_t bh[2][4], bl[2][4];
#pragma unroll
            for (int nip = 0; nip < 2; nip++) {
                const uint32_t bo = b_off + (uint32_t)(nip * 16 * SROW) * 2 + kb;
                ldsm_x4(bh[nip], uBh + bo);
                ldsm_x4(bl[nip], uBl + bo);
            }
#pragma unroll
            for (int mi = 0; mi < 4; mi++) {
                const uint32_t ao = a_off + (uint32_t)(mi * 16 * SROW) * 2 + kb;
                uint32_t ah[4], al[4];
                ldsm_x4(ah, uAh + ao);
                ldsm_x4(al, uAl + ao);
#pragma unroll
                for (int ni = 0; ni < 4; ni++) {
                    const uint32_t b0h = bh[ni >> 1][(ni & 1) * 2];
                    const uint32_t b1h = bh[ni >> 1][(ni & 1) * 2 + 1];
                    const uint32_t b0l = bl[ni >> 1][(ni & 1) * 2];
                    const uint32_t b1l = bl[ni >> 1][(ni & 1) * 2 + 1];
                    mma16816(acc[mi][ni], ah, b0h, b1h);
                    mma16816(acc[mi][ni], ah, b0l, b1l);
                    mma16816(acc[mi][ni], al, b0h, b1h);
                }
            }
        }
        __syncthreads();
    }

#pragma unroll
    for (int mi = 0; mi < 4; mi++) {
#pragma unroll
        for (int ni = 0; ni < 4; ni++) {
#pragma unroll
            for (int half = 0; half < 2; half++) {
                const int m = m_blk + wm * 64 + mi * 16 + (l >> 2) + half * 8;
                const int n = n_blk + wn * 32 + ni * 8 + (l & 3) * 2;
                float vx = acc[mi][ni][half * 2 + 0] + bias[n + 0];
                float vy = acc[mi][ni][half * 2 + 1] + bias[n + 1];
                if (MODE == 0) {
                    *(float2*)&out[(size_t)m * NN + n] = make_float2(vx, vy);
                } else {
                    if (MODE == 1) { vx *= 0.125f; vy *= 0.125f; }
                    const int b = m >> 11, s = m & 2047;
                    const int h = n >> 6, hd = n & 63;
                    const size_t o = ((((size_t)b * HH + h) * SS + s) * HDIM) + hd;
                    __nv_bfloat16 hx = __float2bfloat16(vx);
                    __nv_bfloat16 hy = __float2bfloat16(vy);
                    *(__nv_bfloat162*)&outH[o] = __nv_bfloat162(hx, hy);
                    *(__nv_bfloat162*)&outL[o] = __nv_bfloat162(
                        __float2bfloat16(vx - __bfloat162float(hx)),
                        __float2bfloat16(vy - __bfloat162float(hy)));
                }
            }
        }
    }
#undef G_LOAD
}

// ================= mma.sync flash attention, 2-stage cp.async pipeline =========
#define SRA 72
#define AT_BYTES 18432                   // 128 rows * SRA * 2
#define AMASK_OFF (4 * AT_BYTES)         // 73728
#define ASTAGE_BYTES (4 * AT_BYTES + 18432)  // 92160 (K/V hi/lo + mask)
#define ATT_SMEM (2 * ASTAGE_BYTES)      // 184320

__global__ __launch_bounds__(256) void attn_mma_kernel(
    const char* __restrict__ mask8, const float* __restrict__ cmw,
    const __nv_bfloat16* __restrict__ Qh, const __nv_bfloat16* __restrict__ Ql,
    const __nv_bfloat16* __restrict__ Kh, const __nv_bfloat16* __restrict__ Kl,
    const __nv_bfloat16* __restrict__ Vh, const __nv_bfloat16* __restrict__ Vl,
    __nv_bfloat16* __restrict__ Oh, __nv_bfloat16* __restrict__ Ol)
{
    extern __shared__ char smn[];
    const uint32_t u0 = smem_u32(smn);
    __shared__ float s_bias;

    const int tid = threadIdx.x, wid = tid >> 5, l = tid & 31;
    const int q0 = blockIdx.x * 128, h = blockIdx.y, b = blockIdx.z;

    if (tid == 0) {
        float s = 0.f;
        for (int i = 0; i < 9; i++) s += cmw[i];
        s_bias = s / 9.0f;
    }

    const size_t qkvb = ((size_t)(b * HH + h) * SS) * HDIM;

    // ---- Q prologue (uses stage-0 area, consumed into regs before pipeline) ----
    {
        __nv_bfloat16* sQh = (__nv_bfloat16*)smn;
        __nv_bfloat16* sQl = (__nv_bfloat16*)(smn + AT_BYTES);
#pragma unroll
        for (int it = 0; it < 4; it++) {
            int idx = it * 256 + tid;
            int r = idx >> 3, sg = idx & 7;
            size_t g = qkvb + (size_t)(q0 + r) * HDIM + sg * 8;
            int d = r * SRA + sg * 8;
            *(uint4*)&sQh[d] = *(const uint4*)&Qh[g];
            *(uint4*)&sQl[d] = *(const uint4*)&Ql[g];
        }
    }
    __syncthreads();

    uint32_t qfh[4][4], qfl[4][4];
    const uint32_t qoff = (uint32_t)((wid * 16 + (l & 15)) * SRA + (l >> 4) * 8) * 2;
#pragma unroll
    for (int kc = 0; kc < 4; kc++) {
        ldsm_x4(qfh[kc], u0 + qoff + kc * 32);
        ldsm_x4(qfl[kc], u0 + AT_BYTES + qoff + kc * 32);
    }
    __syncthreads();
    const float mbias = s_bias;

    float mx0 = -1e30f, mx1 = -1e30f, sum0 = 0.f, sum1 = 0.f;
    float acc[8][4];
#pragma unroll
    for (int i = 0; i < 8; i++)
#pragma unroll
        for (int j = 0; j < 4; j++) acc[i][j] = 0.f;

    const uint32_t koff = (uint32_t)(((l & 7) + ((l >> 4) << 3)) * SRA + ((l >> 3) & 1) * 8) * 2;
    const uint32_t voff = (uint32_t)((l & 15) * SRA + (l >> 4) * 8) * 2;
    const int rl0 = wid * 16 + (l >> 2);
    const int rl1 = rl0 + 8;

    // stage loader: K/V hi/lo (16 x 16B) + mask (4 x 16B)
#define A_LOAD(ST, JT) do {                                                        \
        const int j0_ = (JT) * 128;                                                \
        const uint32_t sb_ = u0 + (ST) * ASTAGE_BYTES;                             \
        _Pragma("unroll")                                                          \
        for (int it = 0; it < 4; it++) {                                           \
            int idx = it * 256 + tid;                                              \
            int r = idx >> 3, sg = idx & 7;                                        \
            size_t g = qkvb + (size_t)(j0_ + r) * HDIM + sg * 8;                   \
            uint32_t d = (uint32_t)(r * SRA + sg * 8) * 2;                         \
            cpa16(sb_ + 0 * AT_BYTES + d, Kh + g);                                 \
            cpa16(sb_ + 1 * AT_BYTES + d, Kl + g);                                 \
            cpa16(sb_ + 2 * AT_BYTES + d, Vh + g);                                 \
            cpa16(sb_ + 3 * AT_BYTES + d, Vl + g);                                 \
        }                                                                          \
        _Pragma("unroll")                                                          \
        for (int it = 0; it < 4; it++) {                                           \
            int idx = it * 256 + tid;                                              \
            int r = idx >> 3, c = (idx & 7) * 16;                                  \
            cpa16(sb_ + AMASK_OFF + r * 144 + c,                                   \
                  mask8 + ((size_t)b * SS + q0 + r) * SS + j0_ + c);               \
        }                                                                          \
    } while (0)

    A_LOAD(0, 0);
    CPA_COMMIT();

    for (int jt = 0; jt < 16; jt++) {
        if (jt + 1 < 16) {
            A_LOAD((jt + 1) & 1, jt + 1);
            CPA_COMMIT();
            CPA_WAIT1();
        } else {
            CPA_WAIT0();
        }
        __syncthreads();

        const uint32_t sb = u0 + (jt & 1) * ASTAGE_BYTES;
        const uint32_t uKh = sb, uKl = sb + AT_BYTES;
        const uint32_t uVh = sb + 2 * AT_BYTES, uVl = sb + 3 * AT_BYTES;
        const char* sMask = smn + (jt & 1) * ASTAGE_BYTES + AMASK_OFF;

        // ---- scores ----
        float sc[16][4];
#pragma unroll
        for (int i = 0; i < 16; i++)
#pragma unroll
            for (int j = 0; j < 4; j++) sc[i][j] = 0.f;

#pragma unroll
        for (int kc = 0; kc < 4; kc++) {
#pragma unroll
            for (int nb = 0; nb < 8; nb++) {
                uint32_t bh[4], bl[4];
                uint32_t bo = koff + (uint32_t)(nb * 16 * SRA) * 2 + kc * 32;
                ldsm_x4(bh, uKh + bo);
                ldsm_x4(bl, uKl + bo);
                mma16816(sc[2*nb],   qfh[kc], bh[0], bh[1]);
                mma16816(sc[2*nb],   qfh[kc], bl[0], bl[1]);
                mma16816(sc[2*nb],   qfl[kc], bh[0], bh[1]);
                mma16816(sc[2*nb+1], qfh[kc], bh[2], bh[3]);
                mma16816(sc[2*nb+1], qfh[kc], bl[2], bl[3]);
                mma16816(sc[2*nb+1], qfl[kc], bh[2], bh[3]);
            }
        }

        // ---- bias + mask + online softmax ----
        float rm0 = -1e30f, rm1 = -1e30f;
#pragma unroll
        for (int nf = 0; nf < 16; nf++) {
            int c = nf * 8 + (l & 3) * 2;
            char2 ma = *(char2*)&sMask[rl0 * 144 + c];
            char2 mb = *(char2*)&sMask[rl1 * 144 + c];
            float v0 = sc[nf][0] + mbias;
            float v1 = sc[nf][1] + mbias;
            float v2 = sc[nf][2] + mbias;
            float v3 = sc[nf][3] + mbias;
            sc[nf][0] = ma.x ? v0 : -1e9f;
            sc[nf][1] = ma.y ? v1 : -1e9f;
            sc[nf][2] = mb.x ? v2 : -1e9f;
            sc[nf][3] = mb.y ? v3 : -1e9f;
            rm0 = fmaxf(rm0, fmaxf(sc[nf][0], sc[nf][1]));
            rm1 = fmaxf(rm1, fmaxf(sc[nf][2], sc[nf][3]));
        }
        rm0 = fmaxf(rm0, __shfl_xor_sync(0xffffffffu, rm0, 1));
        rm0 = fmaxf(rm0, __shfl_xor_sync(0xffffffffu, rm0, 2));
        rm1 = fmaxf(rm1, __shfl_xor_sync(0xffffffffu, rm1, 1));
        rm1 = fmaxf(rm1, __shfl_xor_sync(0xffffffffu, rm1, 2));

        float mn0 = fmaxf(mx0, rm0), mn1 = fmaxf(mx1, rm1);
        float corr0 = fexp(mx0 - mn0), corr1 = fexp(mx1 - mn1);
        mx0 = mn0; mx1 = mn1;

        float rs0 = 0.f, rs1 = 0.f;
#pragma unroll
        for (int nf = 0; nf < 16; nf++) {
            float p0 = fexp(sc[nf][0] - mn0);
            float p1 = fexp(sc[nf][1] - mn0);
            float p2 = fexp(sc[nf][2] - mn1);
            float p3 = fexp(sc[nf][3] - mn1);
            sc[nf][0] = p0; sc[nf][1] = p1; sc[nf][2] = p2; sc[nf][3] = p3;
            rs0 += p0 + p1;
            rs1 += p2 + p3;
        }
        rs0 += __shfl_xor_sync(0xffffffffu, rs0, 1);
        rs0 += __shfl_xor_sync(0xffffffffu, rs0, 2);
        rs1 += __shfl_xor_sync(0xffffffffu, rs1, 1);
        rs1 += __shfl_xor_sync(0xffffffffu, rs1, 2);
        sum0 = sum0 * corr0 + rs0;
        sum1 = sum1 * corr1 + rs1;
#pragma unroll
        for (int nf = 0; nf < 8; nf++) {
            acc[nf][0] *= corr0; acc[nf][1] *= corr0;
            acc[nf][2] *= corr1; acc[nf][3] *= corr1;
        }

        // ---- ctx += P . V ----
#pragma unroll
        for (int kc = 0; kc < 8; kc++) {
            uint32_t ah[4], al[4];
            {
                uint32_t t0 = pack_bf16(sc[2*kc][0], sc[2*kc][1]);
                uint32_t t1 = pack_bf16(sc[2*kc][2], sc[2*kc][3]);
                uint32_t t2 = pack_bf16(sc[2*kc+1][0], sc[2*kc+1][1]);
                uint32_t t3 = pack_bf16(sc[2*kc+1][2], sc[2*kc+1][3]);
                ah[0] = t0; ah[1] = t1; ah[2] = t2; ah[3] = t3;
                al[0] = pack_bf16(sc[2*kc][0] - bf16lo_f(t0),   sc[2*kc][1] - bf16hi_f(t0));
                al[1] = pack_bf16(sc[2*kc][2] - bf16lo_f(t1),   sc[2*kc][3] - bf16hi_f(t1));
                al[2] = pack_bf16(sc[2*kc+1][0] - bf16lo_f(t2), sc[2*kc+1][1] - bf16hi_f(t2));
                al[3] = pack_bf16(sc[2*kc+1][2] - bf16lo_f(t3), sc[2*kc+1][3] - bf16hi_f(t3));
            }
            const uint32_t vb = voff + (uint32_t)(kc * 16 * SRA) * 2;
#pragma unroll
            for (int db = 0; db < 4; db++) {
                uint32_t vh[4], vl[4];
                uint32_t vo = vb + db * 32;
                ldsm_x4_t(vh, uVh + vo);
                ldsm_x4_t(vl, uVl + vo);
                mma16816(acc[2*db],   ah, vh[0], vh[1]);
                mma16816(acc[2*db],   ah, vl[0], vl[1]);
                mma16816(acc[2*db],   al, vh[0], vh[1]);
                mma16816(acc[2*db+1], ah, vh[2], vh[3]);
                mma16816(acc[2*db+1], ah, vl[2], vl[3]);
                mma16816(acc[2*db+1], al, vh[2], vh[3]);
            }
        }
        __syncthreads();
    }

    // ---- epilogue ----
    const float inv0 = 1.0f / sum0, inv1 = 1.0f / sum1;
    const size_t rg0 = (size_t)b * SS + q0 + wid * 16 + (l >> 2);
    const size_t rg1 = rg0 + 8;
#pragma unroll
    for (int nf = 0; nf < 8; nf++) {
        const int col = h * 64 + nf * 8 + (l & 3) * 2;
        float c0 = acc[nf][0] * inv0, c1 = acc[nf][1] * inv0;
        float c2 = acc[nf][2] * inv1, c3 = acc[nf][3] * inv1;
        __nv_bfloat16 h0 = __float2bfloat16(c0), h1 = __float2bfloat16(c1);
        __nv_bfloat16 h2 = __float2bfloat16(c2), h3 = __float2bfloat16(c3);
        *(__nv_bfloat162*)&Oh[rg0 * DD + col] = __nv_bfloat162(h0, h1);
        *(__nv_bfloat162*)&Ol[rg0 * DD + col] = __nv_bfloat162(
            __float2bfloat16(c0 - __bfloat162float(h0)),
            __float2bfloat16(c1 - __bfloat162float(h1)));
        *(__nv_bfloat162*)&Oh[rg1 * DD + col] = __nv_bfloat162(h2, h3);
        *(__nv_bfloat162*)&Ol[rg1 * DD + col] = __nv_bfloat162(
            __float2bfloat16(c2 - __bfloat162float(h2)),
            __float2bfloat16(c3 - __bfloat162float(h3)));
    }
#undef A_LOAD
}

// ---------------- launch ----------------
extern "C" void kernel_launch(void* const* d_in, const int* in_sizes, int n_in,
                              void* d_out, int out_size)
{
    const float* x   = (const float*)d_in[0];
    const float* Wq  = (const float*)d_in[1];
    const float* bq  = (const float*)d_in[2];
    const float* Wk  = (const float*)d_in[3];
    const float* bk  = (const float*)d_in[4];
    const float* Wv  = (const float*)d_in[5];
    const float* bv  = (const float*)d_in[6];
    const float* Wo  = (const float*)d_in[7];
    const float* bo  = (const float*)d_in[8];
    const float* cmw = (const float*)d_in[9];
    const int*  mask = (const int*)d_in[10];
    float* out = (float*)d_out;

    void *pQh, *pQl, *pKh, *pKl, *pVh, *pVl, *pAh, *pAl, *pWh, *pWl, *pM8;
    cudaGetSymbolAddress(&pQh, g_Qh);  cudaGetSymbolAddress(&pQl, g_Ql);
    cudaGetSymbolAddress(&pKh, g_Kh);  cudaGetSymbolAddress(&pKl, g_Kl);
    cudaGetSymbolAddress(&pVh, g_Vh);  cudaGetSymbolAddress(&pVl, g_Vl);
    cudaGetSymbolAddress(&pAh, g_Ah);  cudaGetSymbolAddress(&pAl, g_Al);
    cudaGetSymbolAddress(&pWh, g_Wth); cudaGetSymbolAddress(&pWl, g_Wtl);
    cudaGetSymbolAddress(&pM8, g_mask8);
    __nv_bfloat16* Ahp = (__nv_bfloat16*)pAh;
    __nv_bfloat16* Alp = (__nv_bfloat16*)pAl;
    __nv_bfloat16* Whp = (__nv_bfloat16*)pWh;
    __nv_bfloat16* Wlp = (__nv_bfloat16*)pWl;

    static int s_init = 0;
    if (!s_init) {
        cudaFuncSetAttribute(attn_mma_kernel, cudaFuncAttributeMaxDynamicSharedMemorySize, ATT_SMEM);
        cudaFuncSetAttribute(gemm_mma_kernel<0>, cudaFuncAttributeMaxDynamicSharedMemorySize, GSM_BYTES);
        cudaFuncSetAttribute(gemm_mma_kernel<1>, cudaFuncAttributeMaxDynamicSharedMemorySize, GSM_BYTES);
        cudaFuncSetAttribute(gemm_mma_kernel<2>, cudaFuncAttributeMaxDynamicSharedMemorySize, GSM_BYTES);
        s_init = 1;
    }

    const dim3 gg(NN / 128, MTOT / 128);
    const dim3 gw(NN / 32, KK / 32);
    const dim3 bw(32, 8);

    mask8_kernel<<<(BB * SS * SS) / (4 * 256), 256>>>((const int4*)mask, (uint32_t*)pM8);
    convx_kernel<<<(MTOT * KK) / (256 * 4), 256>>>((const float4*)x, Ahp, Alp);

    convW_kernel<<<gw, bw>>>(Wq, Whp, Wlp);
    gemm_mma_kernel<1><<<gg, 256, GSM_BYTES>>>(Ahp, Alp, Whp, Wlp, bq, nullptr,
                                               (__nv_bfloat16*)pQh, (__nv_bfloat16*)pQl);
    convW_kernel<<<gw, bw>>>(Wk, Whp, Wlp);
    gemm_mma_kernel<2><<<gg, 256, GSM_BYTES>>>(Ahp, Alp, Whp, Wlp, bk, nullptr,
                                               (__nv_bfloat16*)pKh, (__nv_bfloat16*)pKl);
    convW_kernel<<<gw, bw>>>(Wv, Whp, Wlp);
    gemm_mma_kernel<2><<<gg, 256, GSM_BYTES>>>(Ahp, Alp, Whp, Wlp, bv, nullptr,
                                               (__nv_bfloat16*)pVh, (__nv_bfloat16*)pVl);

    attn_mma_kernel<<<dim3(SS / 128, HH, BB), 256, ATT_SMEM>>>(
        (const char*)pM8, cmw,
        (const __nv_bfloat16*)pQh, (const __nv_bfloat16*)pQl,
        (const __nv_bfloat16*)pKh, (const __nv_bfloat16*)pKl,
        (const __nv_bfloat16*)pVh, (const __nv_bfloat16*)pVl,
        Ahp, Alp);

    convW_kernel<<<gw, bw>>>(Wo, Whp, Wlp);
    gemm_mma_kernel<0><<<gg, 256, GSM_BYTES>>>(Ahp, Alp, Whp, Wlp, bo, out, nullptr, nullptr);
}